// round 8
// baseline (speedup 1.0000x reference)
#include <cuda_runtime.h>

// LengthRegulator: B=32, T=1024, C=384, M=4096. Durations int32; totals appended
// to out as float32 values (confirmed R4/R5).
//
// R8 design: scatter (run-length expand) instead of gather — block per (b,t)
// loads x row once (no indirection) and streams it to its frame range.

#define BB 32
#define TT 1024
#define CC 384
#define MM 4096
#define C4 (CC / 4)                              // 96 float4 per row
#define MAIN_ELEMS ((long long)BB * MM * CC)     // 50,331,648

__device__ int g_cs[BB][TT];       // inclusive cumsum per batch
__device__ int g_total[BB];        // cs[TT-1]

// ---------------------------------------------------------------------------
// Prep: warp-shfl inclusive scan of durations -> g_cs, g_total, out tail.
// 32 blocks x 1024 threads, ~2 us.
// ---------------------------------------------------------------------------
__global__ void lr_prep_kernel(const int* __restrict__ dur,
                               float* __restrict__ out_base) {
    __shared__ int wsum[32];
    const int b = blockIdx.x;
    const int t = threadIdx.x;
    const int lane = t & 31;
    const int wid = t >> 5;

    int v = dur[b * TT + t];
    #pragma unroll
    for (int off = 1; off < 32; off <<= 1) {
        int n = __shfl_up_sync(0xffffffffu, v, off);
        if (lane >= off) v += n;
    }
    if (lane == 31) wsum[wid] = v;
    __syncthreads();
    if (wid == 0) {
        int s = wsum[lane];
        #pragma unroll
        for (int off = 1; off < 32; off <<= 1) {
            int n = __shfl_up_sync(0xffffffffu, s, off);
            if (lane >= off) s += n;
        }
        wsum[lane] = s;
    }
    __syncthreads();
    const int cs = v + ((wid > 0) ? wsum[wid - 1] : 0);
    g_cs[b][t] = cs;
    if (t == TT - 1) {
        g_total[b] = cs;
        out_base[MAIN_ELEMS + b] = (float)cs;      // total as float32 value
    }
}

// ---------------------------------------------------------------------------
// Scatter: grid (TT, BB), 96 threads (1 float4 per thread = one x row).
// Row address depends only on blockIdx -> load issues immediately, zero
// indirection. Streams the row to frames [cs[t-1], min(cs[t], MM)).
// ---------------------------------------------------------------------------
__global__ void lr_scatter_kernel(const float4* __restrict__ x4,
                                  float4* __restrict__ out4) {
    const int t = blockIdx.x;
    const int b = blockIdx.y;
    const int c = threadIdx.x;                     // 0..95

    int end   = g_cs[b][t];
    int start = (t > 0) ? g_cs[b][t - 1] : 0;
    if (end > MM) end = MM;
    if (start >= end) return;                      // dur==0 or fully clipped

    const float4 v = __ldg(&x4[(b * TT + t) * C4 + c]);

    float4* dst = out4 + ((long long)b * MM + start) * C4 + c;
    for (int f = start; f < end; ++f) {
        __stcs(dst, v);
        dst += C4;
    }
}

// ---------------------------------------------------------------------------
// Zero-fill frames [total, MM). grid (MM/8, BB), 256 threads (8 frames/block,
// 96 float4 each = 768 float4). Blocks entirely below total exit after one
// cached read; only ~12% of blocks store.
// ---------------------------------------------------------------------------
__global__ void lr_zerofill_kernel(float4* __restrict__ out4) {
    const int b = blockIdx.y;
    const int total = g_total[b];
    const int f_base = blockIdx.x * 8;             // first frame of this block
    if (f_base + 8 <= total) return;               // fully valid -> nothing to do

    const float4 z = make_float4(0.f, 0.f, 0.f, 0.f);
    #pragma unroll
    for (int k = 0; k < 3; ++k) {                  // 3 * 256 = 768 float4
        const int e = k * 256 + threadIdx.x;       // 0..767
        const int f = f_base + e / C4;
        if (f >= total && f < MM)
            __stcs(&out4[((long long)b * MM + f_base) * C4 + e], z);
    }
}

// ---------------------------------------------------------------------------

extern "C" void kernel_launch(void* const* d_in, const int* in_sizes, int n_in,
                              void* d_out, int out_size) {
    const float4* x4 = (const float4*)d_in[0];
    const int* dur = (const int*)d_in[1];
    float* out = (float*)d_out;

    lr_prep_kernel<<<BB, TT>>>(dur, out);

    dim3 gs(TT, BB);
    lr_scatter_kernel<<<gs, C4>>>(x4, (float4*)d_out);

    dim3 gz(MM / 8, BB);
    lr_zerofill_kernel<<<gz, 256>>>((float4*)d_out);
}

// round 9
// speedup vs baseline: 1.0427x; 1.0427x over previous
#include <cuda_runtime.h>

// LengthRegulator: B=32, T=1024, C=384, M=4096. Durations int32; totals appended
// to out as float32 values (confirmed R4/R5).
//
// R9: ONE fused kernel. Each block (512 thr) recomputes the per-batch duration
// scan (cheap, L2-hot), resolves tok for its 16 frames into smem, then streams
// 16 frames x 96 float4 of output. No kernel boundaries, no dependent LDG chain.

#define BB 32
#define TT 1024
#define CC 384
#define MM 4096
#define C4 (CC / 4)                              // 96 float4 per row
#define MAIN_ELEMS ((long long)BB * MM * CC)     // 50,331,648
#define FPB 16                                   // frames per block
#define NTHR 512                                 // threads per block
#define EPB (FPB * C4)                           // 1536 float4 per block

__global__ __launch_bounds__(NTHR) void lr_fused_kernel(
        const int2* __restrict__ dur2,           // durations as int2 pairs
        const float4* __restrict__ x4,
        float4* __restrict__ out4,
        float* __restrict__ out_base) {
    __shared__ int cs[TT];
    __shared__ int wsum[32];
    __shared__ int stok[FPB];

    const int b   = blockIdx.y;
    const int tid = threadIdx.x;                 // 0..511
    const int lane = tid & 31;
    const int w    = tid >> 5;                   // warp 0..15

    // ---- scan: thread i owns elements 2i, 2i+1 ----
    const int2 d = dur2[b * (TT / 2) + tid];
    const int e1 = d.y;
    int pair = d.x + d.y;
    #pragma unroll
    for (int off = 1; off < 32; off <<= 1) {
        int n = __shfl_up_sync(0xffffffffu, pair, off);
        if (lane >= off) pair += n;
    }
    if (lane == 31) wsum[w] = pair;              // warp total (pairs 32w..32w+31)
    __syncthreads();
    if (tid < 32) {
        int s = (tid < 16) ? wsum[tid] : 0;
        #pragma unroll
        for (int off = 1; off < 32; off <<= 1) {
            int n = __shfl_up_sync(0xffffffffu, s, off);
            if (lane >= off) s += n;
        }
        if (tid < 16) wsum[tid] = s;             // inclusive over warps
    }
    __syncthreads();
    const int base = (w > 0) ? wsum[w - 1] : 0;
    cs[2 * tid + 1] = base + pair;               // inclusive cumsum
    cs[2 * tid]     = base + pair - e1;
    __syncthreads();

    const int total = cs[TT - 1];
    const int f0 = blockIdx.x * FPB;

    // ---- tok for this block's 16 frames -> smem ----
    if (tid < FPB) {
        const int f = f0 + tid;
        // upper_bound via bit construction: largest pos with cs[pos-1] <= f
        int pos = 0;
        #pragma unroll
        for (int step = TT / 2; step > 0; step >>= 1) {
            int cand = pos + step;               // cand-1 <= 1022
            if (cs[cand - 1] <= f) pos = cand;
        }
        stok[tid] = (f < total) ? pos : -1;
    }
    if (blockIdx.x == 0 && tid == 0)
        out_base[MAIN_ELEMS + b] = (float)total; // total as float32 value
    __syncthreads();

    // ---- stream 16 frames: 3 independent float4 per thread ----
    const int obase = (b * MM + f0) * C4;        // fits int (< 12.6M)
    float4 val[3];
    #pragma unroll
    for (int k = 0; k < 3; ++k) {
        const int e  = k * NTHR + tid;           // 0..1535
        const int fl = e / C4;                   // local frame 0..15
        const int c  = e - fl * C4;
        const int tok = stok[fl];
        val[k] = make_float4(0.f, 0.f, 0.f, 0.f);
        if (tok >= 0) val[k] = __ldg(&x4[(b * TT + tok) * C4 + c]);
    }
    #pragma unroll
    for (int k = 0; k < 3; ++k)
        __stcs(&out4[obase + k * NTHR + tid], val[k]);
}

// ---------------------------------------------------------------------------

extern "C" void kernel_launch(void* const* d_in, const int* in_sizes, int n_in,
                              void* d_out, int out_size) {
    const float4* x4 = (const float4*)d_in[0];
    const int2* dur2 = (const int2*)d_in[1];
    float* out = (float*)d_out;

    dim3 grid(MM / FPB, BB);                     // (256, 32)
    lr_fused_kernel<<<grid, NTHR>>>(dur2, x4, (float4*)d_out, out);
}

// round 10
// speedup vs baseline: 1.1310x; 1.0846x over previous
#include <cuda_runtime.h>

// LengthRegulator: B=32, T=1024, C=384, M=4096. Durations int32; totals appended
// to out as float32 values (confirmed R4/R5).
//
// R10: two kernels. Prep at grid>=148 CTAs (escapes small-grid issue throttle),
// gather kept byte-identical to the best-measured R7 version (38.0us).

#define BB 32
#define TT 1024
#define CC 384
#define MM 4096
#define C4 (CC / 4)                              // 96 float4 per row
#define MAIN_ELEMS ((long long)BB * MM * CC)     // 50,331,648
#define N4 (BB * MM * C4)                        // 12,582,912 float4
#define QTR (N4 / 4)                             // 3,145,728
#define SEG 8                                    // prep blocks per batch
#define FSEG (MM / SEG)                          // 512 frames per prep block

__device__ int g_tok[BB * MM];     // token index per frame, -1 => zero-fill

// ---------------------------------------------------------------------------
// Prep: grid (SEG, BB) = 256 CTAs, 512 threads. Each block scans its batch's
// 1024 durations (int2 pairs, shfl scan) and resolves FSEG frames (1/thread).
// ---------------------------------------------------------------------------
__global__ __launch_bounds__(512) void lr_prep_kernel(
        const int2* __restrict__ dur2,
        float* __restrict__ out_base) {
    __shared__ int cs[TT];
    __shared__ int wsum[16];

    const int b   = blockIdx.y;
    const int tid = threadIdx.x;                 // 0..511
    const int lane = tid & 31;
    const int w    = tid >> 5;                   // warp 0..15

    // scan: thread i owns duration elements 2i, 2i+1
    const int2 d = dur2[b * (TT / 2) + tid];
    const int e1 = d.y;
    int pair = d.x + d.y;
    #pragma unroll
    for (int off = 1; off < 32; off <<= 1) {
        int n = __shfl_up_sync(0xffffffffu, pair, off);
        if (lane >= off) pair += n;
    }
    if (lane == 31) wsum[w] = pair;
    __syncthreads();
    if (tid < 32) {
        int s = (tid < 16) ? wsum[tid] : 0;
        #pragma unroll
        for (int off = 1; off < 32; off <<= 1) {
            int n = __shfl_up_sync(0xffffffffu, s, off);
            if (lane >= off) s += n;
        }
        if (tid < 16) wsum[tid] = s;
    }
    __syncthreads();
    const int base = (w > 0) ? wsum[w - 1] : 0;
    cs[2 * tid + 1] = base + pair;               // inclusive cumsum
    cs[2 * tid]     = base + pair - e1;
    __syncthreads();

    const int total = cs[TT - 1];
    if (blockIdx.x == 0 && tid == 0)
        out_base[MAIN_ELEMS + b] = (float)total; // total as float32 value

    const int f = blockIdx.x * FSEG + tid;       // one frame per thread
    // upper_bound via bit construction: largest pos with cs[pos-1] <= f
    int pos = 0;
    #pragma unroll
    for (int step = TT / 2; step > 0; step >>= 1) {
        int cand = pos + step;                   // cand-1 <= 1022
        if (cs[cand - 1] <= f) pos = cand;
    }
    g_tok[b * MM + f] = (f < total) ? pos : -1;
}

// ---------------------------------------------------------------------------
// Gather (identical to R7 best): 4 independent coalesced float4 streams per
// thread (MLP=4). __stcs streaming stores keep x's read lines resident in L2.
// ---------------------------------------------------------------------------
__global__ void lr_gather_kernel(const float4* __restrict__ x4,
                                 float4* __restrict__ out4) {
    const int i = blockIdx.x * blockDim.x + threadIdx.x;     // < QTR

    int idx[4], tok[4], src[4];
    #pragma unroll
    for (int k = 0; k < 4; ++k) {
        idx[k] = i + k * QTR;
        const int row = idx[k] / C4;               // b * MM + f
        const int c   = idx[k] - row * C4;
        const int b   = row >> 12;
        tok[k] = g_tok[row];
        src[k] = (b * TT + tok[k]) * C4 + c;
    }

    float4 val[4];
    #pragma unroll
    for (int k = 0; k < 4; ++k) {
        val[k] = make_float4(0.f, 0.f, 0.f, 0.f);
        if (tok[k] >= 0) val[k] = __ldg(&x4[src[k]]);
    }

    #pragma unroll
    for (int k = 0; k < 4; ++k)
        __stcs(&out4[idx[k]], val[k]);
}

// ---------------------------------------------------------------------------

extern "C" void kernel_launch(void* const* d_in, const int* in_sizes, int n_in,
                              void* d_out, int out_size) {
    const float4* x4 = (const float4*)d_in[0];
    const int2* dur2 = (const int2*)d_in[1];
    float* out = (float*)d_out;

    dim3 gprep(SEG, BB);                         // (8, 32) = 256 CTAs
    lr_prep_kernel<<<gprep, 512>>>(dur2, out);
    lr_gather_kernel<<<QTR / 256, 256>>>(x4, (float4*)d_out);
}